// round 17
// baseline (speedup 1.0000x reference)
#include <cuda_runtime.h>
#include <cuda_fp16.h>
#include <math.h>
#include <stdint.h>

// ---------------- problem constants ----------------
#define BATCH 2
#define SEQL 4096
#define DMODEL 512
#define DSTATE 64
#define DCONV 4
#define HEADDIM 64
#define DINNER 1024
#define NHEADS 16
#define CONVDIM 1152          // DINNER + 2*DSTATE
#define DPROJ 2192            // 2*DINNER + 2*DSTATE + NHEADS
#define DPROJ_PAD 2304        // padded to multiple of 128
#define ROWS (BATCH*SEQL)     // 8192
#define DFF 2048
#define EPS 1e-5f

#define LCHUNK 256            // time-chunk length for chunked scan
#define NCHK (SEQL/LCHUNK)    // 16

// ---------------- scratch (static device mem; no allocations) ----------------
__device__ __half g_xn   [(size_t)ROWS*DMODEL];
__device__ float  g_zx   [(size_t)ROWS*DPROJ_PAD];
__device__ float  g_dt   [(size_t)BATCH*2*SEQL*NHEADS];
__device__ float  g_dA   [(size_t)BATCH*2*SEQL*NHEADS];
__device__ float  g_y    [(size_t)BATCH*2*SEQL*DINNER];
__device__ __half g_g    [(size_t)ROWS*DINNER];
__device__ float  g_mid  [(size_t)ROWS*DMODEL];
__device__ __half g_m    [(size_t)ROWS*DMODEL];
__device__ __half g_ff1  [(size_t)ROWS*DFF];
// chunked-scan intermediates
__device__ float  g_cum  [(size_t)64*SEQL];                 // per (bdh): within-chunk cumprod dA
__device__ float  g_hend [(size_t)64*NCHK*64*64];           // local end states
__device__ float  g_h0   [(size_t)64*NCHK*64*64];           // chunk start states
__device__ float  g_convC[(size_t)4*SEQL*64];               // conv'd C per (b,d)
// transposed weights [N, K] K-major, fp16
__device__ __half g_inwT [(size_t)DPROJ_PAD*DMODEL];
__device__ __half g_outwT[(size_t)DMODEL*DINNER];
__device__ __half g_ff1T [(size_t)DFF*DMODEL];
__device__ __half g_ff2T [(size_t)DMODEL*DFF];

// ---------------- helpers ----------------
__device__ __forceinline__ float siluf(float x){
    float t;
    asm("tanh.approx.f32 %0, %1;" : "=f"(t) : "f"(0.5f*x));
    return 0.5f*x*(1.f + t);
}

__device__ __forceinline__ uint32_t smem_u32(const void* p){
    uint32_t a;
    asm("{ .reg .u64 t; cvta.to.shared.u64 t, %1; cvt.u32.u64 %0, t; }" : "=r"(a) : "l"(p));
    return a;
}
__device__ __forceinline__ void cp16(void* smem, const void* g){
    unsigned a = smem_u32(smem);
    asm volatile("cp.async.cg.shared.global [%0], [%1], 16;\n" :: "r"(a), "l"(g));
}
__device__ __forceinline__ void cp4(void* smem, const void* g){
    unsigned a = smem_u32(smem);
    asm volatile("cp.async.ca.shared.global [%0], [%1], 4;\n" :: "r"(a), "l"(g));
}

__device__ __forceinline__ void mma_f16(float* d, const uint32_t* a, const uint32_t* b){
    asm volatile(
        "mma.sync.aligned.m16n8k16.row.col.f32.f16.f16.f32 "
        "{%0,%1,%2,%3}, {%4,%5,%6,%7}, {%8,%9}, {%0,%1,%2,%3};"
        : "+f"(d[0]), "+f"(d[1]), "+f"(d[2]), "+f"(d[3])
        : "r"(a[0]), "r"(a[1]), "r"(a[2]), "r"(a[3]), "r"(b[0]), "r"(b[1]));
}

// ---------------- prep: batched weight transpose + input layernorm ----------------
__global__ __launch_bounds__(256) void prep_kernel(
    const float* __restrict__ in_w,  const float* __restrict__ out_w,
    const float* __restrict__ ff_w1, const float* __restrict__ ff_w2,
    const float* __restrict__ x, const float* __restrict__ nin_w,
    const float* __restrict__ nin_b)
{
    __shared__ float t[32][33];
    int tid = threadIdx.x;
    if (blockIdx.x < 3712){
        int tile = blockIdx.x;
        const float* in; __half* out; int K, N0, ktiles;
        if (tile < 1152){                    in = in_w;  out = g_inwT;  K = DMODEL; N0 = DPROJ;  ktiles = 16; }
        else if (tile < 1664){ tile -= 1152; in = out_w; out = g_outwT; K = DINNER; N0 = DMODEL; ktiles = 32; }
        else if (tile < 2688){ tile -= 1664; in = ff_w1; out = g_ff1T;  K = DMODEL; N0 = DFF;    ktiles = 16; }
        else {                 tile -= 2688; in = ff_w2; out = g_ff2T;  K = DFF;    N0 = DMODEL; ktiles = 64; }
        int kb = (tile % ktiles)*32, nb = (tile / ktiles)*32;
        int xx = tid & 31, yy = tid >> 5;
        #pragma unroll
        for (int i=0;i<32;i+=8){
            int k = kb + yy + i, n = nb + xx;
            t[yy+i][xx] = (n < N0) ? in[(size_t)k*N0 + n] : 0.f;
        }
        __syncthreads();
        #pragma unroll
        for (int i=0;i<32;i+=8){
            int n = nb + yy + i, k = kb + xx;
            out[(size_t)n*K + k] = __float2half_rn(t[xx][yy+i]);
        }
    } else {
        int row = (blockIdx.x - 3712)*8 + (tid>>5);
        int lane = tid & 31;
        const float* xr = x + (size_t)row*DMODEL;
        float v[16]; float s = 0.f;
        #pragma unroll
        for (int i=0;i<16;i++){ v[i] = xr[lane + 32*i]; s += v[i]; }
        #pragma unroll
        for (int o=16;o;o>>=1) s += __shfl_xor_sync(0xffffffffu, s, o);
        float mu = s * (1.f/DMODEL);
        float s2 = 0.f;
        #pragma unroll
        for (int i=0;i<16;i++){ float d = v[i]-mu; s2 += d*d; }
        #pragma unroll
        for (int o=16;o;o>>=1) s2 += __shfl_xor_sync(0xffffffffu, s2, o);
        float inv = rsqrtf(s2*(1.f/DMODEL) + EPS);
        __half* orow = g_xn + (size_t)row*DMODEL;
        #pragma unroll
        for (int i=0;i<16;i++){
            int c = lane + 32*i;
            orow[c] = __float2half_rn((v[i]-mu)*inv*nin_w[c] + nin_b[c]);
        }
    }
}

// ---------------- layernorm (warp per 512-row), fp16 output ----------------
__global__ void ln_kernel(const float* __restrict__ x, const float* __restrict__ w,
                          const float* __restrict__ b, __half* __restrict__ out){
    int row = blockIdx.x*(blockDim.x>>5) + (threadIdx.x>>5);
    int lane = threadIdx.x & 31;
    if (row >= ROWS) return;
    const float* xr = x + (size_t)row*DMODEL;
    float v[16]; float s = 0.f;
    #pragma unroll
    for (int i=0;i<16;i++){ v[i] = xr[lane + 32*i]; s += v[i]; }
    #pragma unroll
    for (int o=16;o;o>>=1) s += __shfl_xor_sync(0xffffffffu, s, o);
    float mu = s * (1.f/DMODEL);
    float s2 = 0.f;
    #pragma unroll
    for (int i=0;i<16;i++){ float d = v[i]-mu; s2 += d*d; }
    #pragma unroll
    for (int o=16;o;o>>=1) s2 += __shfl_xor_sync(0xffffffffu, s2, o);
    float inv = rsqrtf(s2*(1.f/DMODEL) + EPS);
    __half* orow = out + (size_t)row*DMODEL;
    #pragma unroll
    for (int i=0;i<16;i++){
        int c = lane + 32*i;
        orow[c] = __float2half_rn((v[i]-mu)*inv*w[c] + b[c]);
    }
}

// ---------------- fp16 mma.sync GEMM (6-stage, 2 K-steps per barrier) ----------------
#define GST 6
#define HROWSTR 24
#define HSTAGE_H (128*HROWSTR)
#define GSMEM_BYTES (2*GST*HSTAGE_H*2)     // 73728

template<int EPI>
__global__ __launch_bounds__(256) void mma_gemm(
    const __half* __restrict__ A, const __half* __restrict__ Bw,
    float* __restrict__ C, __half* __restrict__ Ch,
    int K, int N, const float* __restrict__ bias, const float* __restrict__ res)
{
    extern __shared__ __half hsm[];
    __half* sAb = hsm;
    __half* sBb = hsm + GST*HSTAGE_H;

    int tid = threadIdx.x, lane = tid & 31, wid = tid >> 5;
    int bm = blockIdx.y * 128, bn = blockIdx.x * 128;
    int wm = (wid >> 1) * 32, wn = (wid & 1) * 64;
    int grp = lane >> 2, tig = lane & 3;

    float acc[2][8][4];
    #pragma unroll
    for (int mi=0;mi<2;mi++)
        #pragma unroll
        for (int ni=0;ni<8;ni++)
            #pragma unroll
            for (int u=0;u<4;u++) acc[mi][ni][u] = 0.f;

    int lrow = tid >> 1, lc = tid & 1;
    auto load = [&](int st, int k0){
        cp16(&sAb[st*HSTAGE_H + lrow*HROWSTR + lc*8], A + (size_t)(bm+lrow)*K + k0 + lc*8);
        cp16(&sBb[st*HSTAGE_H + lrow*HROWSTR + lc*8], Bw + (size_t)(bn+lrow)*K + k0 + lc*8);
        asm volatile("cp.async.commit_group;\n");
    };

    int nk = K >> 4;
    #pragma unroll
    for (int s=0;s<4;s++) load(s, s << 4);

    int nk2 = nk >> 1;
    for (int it = 0; it < nk2; it++){
        asm volatile("cp.async.wait_group 2;\n");
        __syncthreads();
        int kt0 = it*2;
        int nx = kt0 + 4;
        if (nx < nk) load(nx % GST, nx << 4);
        else         asm volatile("cp.async.commit_group;\n");
        if (nx+1 < nk) load((nx+1) % GST, (nx+1) << 4);
        else           asm volatile("cp.async.commit_group;\n");

        #pragma unroll
        for (int s2 = 0; s2 < 2; s2++){
            const __half* as = sAb + ((kt0+s2) % GST)*HSTAGE_H;
            const __half* bs = sBb + ((kt0+s2) % GST)*HSTAGE_H;
            uint32_t af[2][4], bf[8][2];
            #pragma unroll
            for (int mi=0;mi<2;mi++){
                int r = wm + mi*16 + grp;
                af[mi][0] = *(const uint32_t*)&as[r*HROWSTR     + tig*2];
                af[mi][1] = *(const uint32_t*)&as[(r+8)*HROWSTR + tig*2];
                af[mi][2] = *(const uint32_t*)&as[r*HROWSTR     + tig*2 + 8];
                af[mi][3] = *(const uint32_t*)&as[(r+8)*HROWSTR + tig*2 + 8];
            }
            #pragma unroll
            for (int ni=0;ni<8;ni++){
                int c0 = wn + ni*8 + grp;
                bf[ni][0] = *(const uint32_t*)&bs[c0*HROWSTR + tig*2];
                bf[ni][1] = *(const uint32_t*)&bs[c0*HROWSTR + tig*2 + 8];
            }
            #pragma unroll
            for (int mi=0;mi<2;mi++)
                #pragma unroll
                for (int ni=0;ni<8;ni++)
                    mma_f16(acc[mi][ni], af[mi], bf[ni]);
        }
    }

    #pragma unroll
    for (int mi=0;mi<2;mi++){
        #pragma unroll
        for (int half2_=0; half2_<2; half2_++){
            int row = bm + wm + mi*16 + grp + half2_*8;
            #pragma unroll
            for (int ni=0;ni<8;ni++){
                int col = bn + wn + ni*8 + tig*2;
                float v0 = acc[mi][ni][half2_*2+0];
                float v1 = acc[mi][ni][half2_*2+1];
                if (EPI == 1){
                    v0 += bias[col];   v1 += bias[col+1];
                    v0 = 0.5f*v0*(1.f + erff(v0*0.70710678118654752f));
                    v1 = 0.5f*v1*(1.f + erff(v1*0.70710678118654752f));
                    __half2 hv; hv.x = __float2half_rn(v0); hv.y = __float2half_rn(v1);
                    *(__half2*)(Ch + (size_t)row*N + col) = hv;
                } else {
                    if (EPI == 2){
                        v0 += bias[col]   + res[(size_t)row*N + col];
                        v1 += bias[col+1] + res[(size_t)row*N + col+1];
                    }
                    float2 v; v.x = v0; v.y = v1;
                    *(float2*)(C + (size_t)row*N + col) = v;
                }
            }
        }
    }
}

// ---------------- dt / dA from fp16 xn ----------------
__global__ void dtda_kernel(const float* __restrict__ in_w,
                            const float* __restrict__ dt_bias,
                            const float* __restrict__ A_log){
    int row = blockIdx.x*16 + (threadIdx.x >> 4);
    int h = threadIdx.x & 15;
    const __half* xr = g_xn + (size_t)row*DMODEL;
    const float* wc = in_w + 2176 + h;
    float acc = dt_bias[h];
    #pragma unroll 8
    for (int k = 0; k < DMODEL; k++)
        acc += __half2float(xr[k]) * wc[(size_t)k*DPROJ];
    float dt = (acc > 20.f) ? acc : log1pf(__expf(acc));
    float dA = __expf(-__expf(A_log[h]) * dt);
    int b = row >> 12, t = row & (SEQL-1);
    size_t i0 = ((size_t)(b*2+0)*SEQL + t)*NHEADS + h;
    size_t i1 = ((size_t)(b*2+1)*SEQL + (SEQL-1-t))*NHEADS + h;
    g_dt[i0] = dt; g_dA[i0] = dA;
    g_dt[i1] = dt; g_dA[i1] = dA;
}

// ---------------- cumdA: within-chunk running product of dA ----------------
// 1024 threads = 64 bdh x 16 chunks; serial over 256 steps
__global__ void cumda_kernel(){
    int idx = blockIdx.x*256 + threadIdx.x;   // grid 4
    int bdh = idx >> 4, chunk = idx & 15;
    int bd = bdh >> 4, h = bdh & 15;
    float cum = 1.f;
    #pragma unroll 8
    for (int sl = 0; sl < LCHUNK; sl++){
        int s = chunk*LCHUNK + sl;
        cum *= g_dA[((size_t)bd*SEQL + s)*NHEADS + h];
        g_cum[(size_t)bdh*SEQL + s] = cum;
    }
}

// ---------------- pass A: local scan per time-chunk w/ fused conv+silu ----------------
// grid (128, NCHK): x = (b,d,h,half), y = chunk. CTA: 32 p-rows x 64 states, CHUNK=32 substeps.
#define CHUNK 32
#define LNCHUNK (LCHUNK/CHUNK)      // 8
#define NCH 160
#define RROWS (CHUNK + DCONV - 1)   // 35
#define SC_SRAW 0
#define SC_SCONV (2*RROWS*NCH)
#define SC_SCW   (SC_SCONV + CHUNK*NCH)
#define SC_SCB   (SC_SCW + 4*NCH)
#define SC_SDT   (SC_SCB + NCH)
#define SC_SDA   (SC_SDT + 2*CHUNK)
#define SC_TOTAL (SC_SDA + 2*CHUNK)
#define SC_BYTES (SC_TOTAL*4)

__global__ __launch_bounds__(256) void scan3_kernel(const float* __restrict__ Dh,
                                                    const float* __restrict__ cw,
                                                    const float* __restrict__ cb){
    extern __shared__ float ssm[];
    float* sraw  = ssm + SC_SRAW;
    float* sconv = ssm + SC_SCONV;
    float* scw   = ssm + SC_SCW;
    float* scb   = ssm + SC_SCB;
    float* sdt   = ssm + SC_SDT;
    float* sdA   = ssm + SC_SDA;

    int bx = blockIdx.x;
    int chunk = blockIdx.y;
    int half = bx & 1, h = (bx >> 1) & 15, d = (bx >> 5) & 1, b = bx >> 6;
    int bd = b*2 + d, bdh = b*32 + d*16 + h;
    int tid = threadIdx.x;
    int p = tid >> 3, q = tid & 7;

    for (int ch = tid; ch < NCH; ch += 256){
        int cc = ch < 32 ? h*64 + half*32 + ch
               : (ch < 96 ? 1024 + (ch-32) : 1088 + (ch-96));
        scb[ch] = cb[cc];
        #pragma unroll
        for (int k=0;k<4;k++) scw[k*NCH + ch] = cw[k*CONVDIM + cc];
    }
    for (int j = tid; j < 3*NCH; j += 256) sraw[j] = 0.f;   // boundary (chunk 0)
    __syncthreads();

    const float* zxb = g_zx + (size_t)b*SEQL*DPROJ_PAD;
    const float* dtb = g_dt + ((size_t)bd)*SEQL*NHEADS + h;
    const float* dab = g_dA + ((size_t)bd)*SEQL*NHEADS + h;
    float* ybase = g_y + ((size_t)bd)*SEQL*DINNER;
    int ycol = h*HEADDIM + half*32 + p;
    int s_base = chunk*LCHUNK;

    float hreg[8];
    #pragma unroll
    for (int i=0;i<8;i++) hreg[i] = 0.f;
    float Dhh = Dh[h];

    auto issue = [&](int c, int sbuf){
        int s0 = s_base + c*CHUNK;
        float* dst = sraw + sbuf*RROWS*NCH;
        #pragma unroll
        for (int it=0; it<6; it++){
            int j = tid + it*256;
            if (j < RROWS*40){
                int r = j / 40, seg = j % 40;
                int off = seg*4;
                int u = s0 - 3 + r;
                if (u >= 0){
                    int t = d ? (SEQL-1-u) : u;
                    const float* rowp = zxb + (size_t)t*DPROJ_PAD;
                    const float* src;
                    if (off < 32)      src = rowp + 1024 + h*64 + half*32 + off;
                    else if (off < 96) src = rowp + 2048 + (off-32);
                    else               src = rowp + 2112 + (off-96);
                    cp16(&dst[r*NCH + off], src);
                }
            }
        }
        if (tid < CHUNK)            cp4(&sdt[sbuf*CHUNK + tid],       dtb + (size_t)(s0+tid)*NHEADS);
        else if (tid < 2*CHUNK)     cp4(&sdA[sbuf*CHUNK + tid-CHUNK], dab + (size_t)(s0+tid-CHUNK)*NHEADS);
        asm volatile("cp.async.commit_group;\n");
    };

    issue(0, 0);
    for (int c=0;c<LNCHUNK;c++){
        int cur = c & 1, nxt = cur ^ 1;
        asm volatile("cp.async.wait_group 0;\n");
        __syncthreads();
        if (c+1 < LNCHUNK) issue(c+1, nxt);
        const float* rawc = sraw + cur*RROWS*NCH;
        #pragma unroll
        for (int it=0; it<5; it++){
            int j = tid + it*256;
            int st = j / 40, c4 = j - st*40;
            float4 a = *(const float4*)&scb[c4*4];
            #pragma unroll
            for (int k=0;k<4;k++){
                float4 w4 = *(const float4*)&scw[k*NCH + c4*4];
                float4 r4 = *(const float4*)&rawc[(st+k)*NCH + c4*4];
                a.x += w4.x*r4.x; a.y += w4.y*r4.y; a.z += w4.z*r4.z; a.w += w4.w*r4.w;
            }
            a.x = siluf(a.x); a.y = siluf(a.y); a.z = siluf(a.z); a.w = siluf(a.w);
            *(float4*)&sconv[st*NCH + c4*4] = a;
        }
        __syncthreads();
        // one CTA per (b,d,chunk) exports conv'd C channels for pass C
        if (h == 0 && half == 0){
            int s0 = s_base + c*CHUNK;
            #pragma unroll
            for (int j = tid; j < CHUNK*16; j += 256){
                int k = j >> 4, f4 = j & 15;
                *(float4*)&g_convC[((size_t)bd*SEQL + s0 + k)*64 + f4*4] =
                    *(const float4*)&sconv[k*NCH + 96 + f4*4];
            }
        }
        #pragma unroll 4
        for (int k=0;k<CHUNK;k++){
            const float* row = sconv + k*NCH;
            float dt = sdt[cur*CHUNK + k], dA = sdA[cur*CHUNK + k];
            float xh = row[p];
            float dtx = dt*xh;
            const float4* Bp4 = (const float4*)(row + 32 + q*8);
            const float4* Cp4 = (const float4*)(row + 96 + q*8);
            float4 b0 = Bp4[0], b1 = Bp4[1];
            float4 c0 = Cp4[0], c1 = Cp4[1];
            float bv[8] = {b0.x,b0.y,b0.z,b0.w,b1.x,b1.y,b1.z,b1.w};
            float cv[8] = {c0.x,c0.y,c0.z,c0.w,c1.x,c1.y,c1.z,c1.w};
            float acc = 0.f;
            #pragma unroll
            for (int i=0;i<8;i++){
                hreg[i] = hreg[i]*dA + dtx*bv[i];
                acc += hreg[i]*cv[i];
            }
            acc += __shfl_xor_sync(0xffffffffu, acc, 1);
            acc += __shfl_xor_sync(0xffffffffu, acc, 2);
            acc += __shfl_xor_sync(0xffffffffu, acc, 4);
            if (q == 0){
                int s = s_base + c*CHUNK + k;
                int t = d ? (SEQL-1-s) : s;
                ybase[(size_t)t*DINNER + ycol] = acc + Dhh*xh;
            }
        }
    }
    // export local end state
    size_t ho = (((size_t)bdh*NCHK + chunk)*64 + (half*32 + p))*64 + q*8;
    *(float4*)&g_hend[ho]   = make_float4(hreg[0],hreg[1],hreg[2],hreg[3]);
    *(float4*)&g_hend[ho+4] = make_float4(hreg[4],hreg[5],hreg[6],hreg[7]);
}

// ---------------- pass B: propagate chunk start states ----------------
// grid 1024 x 256: each thread owns one (bdh, p, n) entry, loops chunks
__global__ void h0prop_kernel(){
    int bdh = blockIdx.x >> 4, part = blockIdx.x & 15;
    int e = part*256 + threadIdx.x;          // 0..4095
    float h0 = 0.f;
    #pragma unroll
    for (int c = 0; c < NCHK; c++){
        size_t off = (((size_t)bdh*NCHK + c)*64)*64 + e;
        g_h0[off] = h0;
        float P = g_cum[(size_t)bdh*SEQL + c*LCHUNK + LCHUNK - 1];
        h0 = h0*P + g_hend[off];
    }
}

// ---------------- pass C: y correction  y_t += cumdA_t * (C_t . h0) ----------------
// grid (128, NCHK-1): chunk = y+1. h0 in registers, steps independent.
__global__ __launch_bounds__(256) void ycorr_kernel(){
    __shared__ float scc[2][CHUNK*64];
    __shared__ float scum[2][CHUNK];

    int bx = blockIdx.x;
    int chunk = blockIdx.y + 1;
    int half = bx & 1, h = (bx >> 1) & 15, d = (bx >> 5) & 1, b = bx >> 6;
    int bd = b*2 + d, bdh = b*32 + d*16 + h;
    int tid = threadIdx.x;
    int p = tid >> 3, q = tid & 7;

    float h0r[8];
    {
        size_t ho = (((size_t)bdh*NCHK + chunk)*64 + (half*32 + p))*64 + q*8;
        float4 a = *(const float4*)&g_h0[ho];
        float4 c = *(const float4*)&g_h0[ho+4];
        h0r[0]=a.x; h0r[1]=a.y; h0r[2]=a.z; h0r[3]=a.w;
        h0r[4]=c.x; h0r[5]=c.y; h0r[6]=c.z; h0r[7]=c.w;
    }
    int ycol = h*HEADDIM + half*32 + p;
    float* ybase = g_y + ((size_t)bd)*SEQL*DINNER;

    auto issue = [&](int sc, int buf){
        int s0 = chunk*LCHUNK + sc*CHUNK;
        #pragma unroll
        for (int it=0; it<2; it++){
            int j = tid + it*256;            // 0..511 = 32 steps x 16 float4
            int k = j >> 4, f4 = j & 15;
            cp16(&scc[buf][k*64 + f4*4], &g_convC[((size_t)bd*SEQL + s0 + k)*64 + f4*4]);
        }
        if (tid < CHUNK) cp4(&scum[buf][tid], &g_cum[(size_t)bdh*SEQL + s0 + tid]);
        asm volatile("cp.async.commit_group;\n");
    };

    issue(0, 0);
    for (int sc = 0; sc < LNCHUNK; sc++){
        int cur = sc & 1, nxt = cur ^ 1;
        asm volatile("cp.async.wait_group 0;\n");
        __syncthreads();
        if (sc+1 < LNCHUNK) issue(sc+1, nxt);
        #pragma unroll 4
        for (int k=0;k<CHUNK;k++){
            const float4* cv4 = (const float4*)&scc[cur][k*64 + q*8];
            float4 c0 = cv4[0], c1 = cv4[1];
            float acc = h0r[0]*c0.x + h0r[1]*c0.y + h0r[2]*c0.z + h0r[3]*c0.w
                      + h0r[4]*c1.x + h0r[5]*c1.y + h0r[6]*c1.z + h0r[7]*c1.w;
            acc += __shfl_xor_sync(0xffffffffu, acc, 1);
            acc += __shfl_xor_sync(0xffffffffu, acc, 2);
            acc += __shfl_xor_sync(0xffffffffu, acc, 4);
            if (q == 0){
                int s = chunk*LCHUNK + sc*CHUNK + k;
                int t = d ? (SEQL-1-s) : s;
                size_t yi = (size_t)t*DINNER + ycol;
                ybase[yi] += scum[cur][k]*acc;
            }
        }
    }
}

// ---------------- gate (silu(z)), per-direction RMS norm, combine -> fp16 ----------------
__global__ void gate_kernel(const float* __restrict__ mw){
    int row = blockIdx.x;
    int b = row >> 12, t = row & (SEQL-1);
    int c = threadIdx.x * 4;
    const float4 zz4 = *(const float4*)(g_zx + (size_t)row*DPROJ_PAD + c);
    const float4 y04 = *(const float4*)(g_y + ((size_t)(b*2+0)*SEQL + t)*DINNER + c);
    const float4 y14 = *(const float4*)(g_y + ((size_t)(b*2+1)*SEQL + t)*DINNER + c);
    float g0[4], g1[4];
    float z_[4] = {zz4.x, zz4.y, zz4.z, zz4.w};
    float a0[4] = {y04.x, y04.y, y04.z, y04.w};
    float a1[4] = {y14.x, y14.y, y14.z, y14.w};
    float ss0 = 0.f, ss1 = 0.f;
    #pragma unroll
    for (int j=0;j<4;j++){
        float sz = siluf(z_[j]);
        g0[j] = a0[j]*sz; g1[j] = a1[j]*sz;
        ss0 += g0[j]*g0[j]; ss1 += g1[j]*g1[j];
    }
    #pragma unroll
    for (int o=16;o;o>>=1){
        ss0 += __shfl_xor_sync(0xffffffffu, ss0, o);
        ss1 += __shfl_xor_sync(0xffffffffu, ss1, o);
    }
    __shared__ float red[16];
    int wid = threadIdx.x >> 5, lane = threadIdx.x & 31;
    if (lane == 0){ red[wid] = ss0; red[8+wid] = ss1; }
    __syncthreads();
    if (threadIdx.x == 0){
        float a=0.f, bb=0.f;
        #pragma unroll
        for (int w=0;w<8;w++){ a += red[w]; bb += red[8+w]; }
        red[0] = a; red[8] = bb;
    }
    __syncthreads();
    float r0 = rsqrtf(red[0]*(1.f/DINNER) + EPS);
    float r1 = rsqrtf(red[8]*(1.f/DINNER) + EPS);
    __half2 h0, h1;
    h0.x = __float2half_rn((g0[0]*r0 + g1[0]*r1) * mw[c+0]);
    h0.y = __float2half_rn((g0[1]*r0 + g1[1]*r1) * mw[c+1]);
    h1.x = __float2half_rn((g0[2]*r0 + g1[2]*r1) * mw[c+2]);
    h1.y = __float2half_rn((g0[3]*r0 + g1[3]*r1) * mw[c+3]);
    __half2* go = (__half2*)(g_g + (size_t)row*DINNER + c);
    go[0] = h0; go[1] = h1;
}

// ---------------- launch ----------------
extern "C" void kernel_launch(void* const* d_in, const int* in_sizes, int n_in,
                              void* d_out, int out_size)
{
    const float* x        = (const float*)d_in[0];
    const float* nin_w    = (const float*)d_in[1];
    const float* nin_b    = (const float*)d_in[2];
    const float* nout_w   = (const float*)d_in[3];
    const float* nout_b   = (const float*)d_in[4];
    const float* in_w     = (const float*)d_in[5];
    const float* conv_w   = (const float*)d_in[6];
    const float* conv_b   = (const float*)d_in[7];
    const float* dt_bias  = (const float*)d_in[8];
    const float* A_log    = (const float*)d_in[9];
    const float* D_h      = (const float*)d_in[10];
    const float* mnorm_w  = (const float*)d_in[11];
    const float* out_w    = (const float*)d_in[12];
    const float* ff_w1    = (const float*)d_in[13];
    const float* ff_b1    = (const float*)d_in[14];
    const float* ff_w2    = (const float*)d_in[15];
    const float* ff_b2    = (const float*)d_in[16];
    float* out = (float*)d_out;

    float *p_zx, *p_mid;
    __half *p_xn, *p_g, *p_m, *p_ff1;
    __half *p_inwT, *p_outwT, *p_ff1T, *p_ff2T;
    cudaGetSymbolAddress((void**)&p_xn,   g_xn);
    cudaGetSymbolAddress((void**)&p_zx,   g_zx);
    cudaGetSymbolAddress((void**)&p_g,    g_g);
    cudaGetSymbolAddress((void**)&p_mid,  g_mid);
    cudaGetSymbolAddress((void**)&p_m,    g_m);
    cudaGetSymbolAddress((void**)&p_ff1,  g_ff1);
    cudaGetSymbolAddress((void**)&p_inwT, g_inwT);
    cudaGetSymbolAddress((void**)&p_outwT,g_outwT);
    cudaGetSymbolAddress((void**)&p_ff1T, g_ff1T);
    cudaGetSymbolAddress((void**)&p_ff2T, g_ff2T);

    cudaFuncSetAttribute(mma_gemm<0>, cudaFuncAttributeMaxDynamicSharedMemorySize, GSMEM_BYTES);
    cudaFuncSetAttribute(mma_gemm<1>, cudaFuncAttributeMaxDynamicSharedMemorySize, GSMEM_BYTES);
    cudaFuncSetAttribute(mma_gemm<2>, cudaFuncAttributeMaxDynamicSharedMemorySize, GSMEM_BYTES);
    cudaFuncSetAttribute(scan3_kernel, cudaFuncAttributeMaxDynamicSharedMemorySize, SC_BYTES);

    // 1. prep: weight transposes + input layernorm
    prep_kernel<<<4736, 256>>>(in_w, out_w, ff_w1, ff_w2, x, nin_w, nin_b);

    // 2. in-proj
    mma_gemm<0><<<dim3(DPROJ_PAD/128, ROWS/128), 256, GSMEM_BYTES>>>(
        p_xn, p_inwT, p_zx, nullptr, DMODEL, DPROJ_PAD, nullptr, nullptr);

    // 3. dt/dA
    dtda_kernel<<<ROWS/16, 256>>>(in_w, dt_bias, A_log);

    // 4. within-chunk cumprod of dA
    cumda_kernel<<<4, 256>>>();

    // 5. pass A: chunk-local scans (2048 CTAs)
    scan3_kernel<<<dim3(128, NCHK), 256, SC_BYTES>>>(D_h, conv_w, conv_b);

    // 6. pass B: propagate chunk boundary states
    h0prop_kernel<<<1024, 256>>>();

    // 7. pass C: y correction
    ycorr_kernel<<<dim3(128, NCHK-1), 256>>>();

    // 8. gate + per-dir rmsnorm + combine
    gate_kernel<<<ROWS, 256>>>(mnorm_w);

    // 9. out-proj
    mma_gemm<0><<<dim3(DMODEL/128, ROWS/128), 256, GSMEM_BYTES>>>(
        p_g, p_outwT, p_mid, nullptr, DINNER, DMODEL, nullptr, nullptr);

    // 10. layernorm out
    ln_kernel<<<ROWS/8, 256>>>(p_mid, nout_w, nout_b, p_m);

    // 11. FF1 + gelu
    mma_gemm<1><<<dim3(DFF/128, ROWS/128), 256, GSMEM_BYTES>>>(
        p_m, p_ff1T, nullptr, p_ff1, DMODEL, DFF, ff_b1, nullptr);

    // 12. FF2 + bias + residual(x)
    mma_gemm<2><<<dim3(DMODEL/128, ROWS/128), 256, GSMEM_BYTES>>>(
        p_ff1, p_ff2T, out, nullptr, DFF, DMODEL, ff_b2, x);
}